// round 11
// baseline (speedup 1.0000x reference)
#include <cuda_runtime.h>
#include <cuda_bf16.h>
#include <cstdint>

// Problem constants
#define BATCH  4
#define SEQ    2048
#define DMODEL 1024
#define NHEAD  16
#define DHEAD  64
#define MTOT   (BATCH * SEQ)   // 8192 rows
#define KDIM   DMODEL

// ---------------------------------------------------------------------------
// Scratch (__device__ globals — the sanctioned no-alloc path)
// ---------------------------------------------------------------------------
__device__ float g_q[(size_t)MTOT * DMODEL];
__device__ float g_k[(size_t)MTOT * DMODEL];
__device__ float g_v[(size_t)MTOT * DMODEL];
__device__ float g_ctx[(size_t)MTOT * DMODEL];
__device__ __nv_bfloat16 g_aHi[(size_t)MTOT * DMODEL];
__device__ __nv_bfloat16 g_aLo[(size_t)MTOT * DMODEL];
__device__ __nv_bfloat16 g_bHi[(size_t)DMODEL * DMODEL];
__device__ __nv_bfloat16 g_bLo[(size_t)DMODEL * DMODEL];

// ---------------------------------------------------------------------------
// Helpers (baseline compute_103 PTX only — no tcgen05/TMEM in this harness)
// ---------------------------------------------------------------------------
__device__ __forceinline__ uint32_t smem_u32(const void* p) {
    uint32_t a;
    asm("{ .reg .u64 t; cvta.to.shared.u64 t, %1; cvt.u32.u64 %0, t; }"
        : "=r"(a) : "l"(p));
    return a;
}
__device__ __forceinline__ void ldsm4(uint32_t* r, uint32_t addr) {
    asm volatile("ldmatrix.sync.aligned.m8n8.x4.shared.b16 {%0,%1,%2,%3}, [%4];"
                 : "=r"(r[0]), "=r"(r[1]), "=r"(r[2]), "=r"(r[3]) : "r"(addr));
}
__device__ __forceinline__ void mma16816(float* d, const uint32_t* a, const uint32_t* b) {
    asm volatile(
        "mma.sync.aligned.m16n8k16.row.col.f32.bf16.bf16.f32 "
        "{%0,%1,%2,%3}, {%4,%5,%6,%7}, {%8,%9}, {%0,%1,%2,%3};"
        : "+f"(d[0]), "+f"(d[1]), "+f"(d[2]), "+f"(d[3])
        : "r"(a[0]), "r"(a[1]), "r"(a[2]), "r"(a[3]), "r"(b[0]), "r"(b[1]));
}
__device__ __forceinline__ uint32_t pack_bf2(__nv_bfloat16 a, __nv_bfloat16 b) {
    __nv_bfloat162 t = __halves2bfloat162(a, b);
    return *(uint32_t*)&t;
}
__device__ __forceinline__ void cpasync16(uint32_t dst, const void* src) {
    asm volatile("cp.async.ca.shared.global [%0], [%1], 16;"
                 :: "r"(dst), "l"(src) : "memory");
}
__device__ __forceinline__ void cp_commit() {
    asm volatile("cp.async.commit_group;" ::: "memory");
}
__device__ __forceinline__ void cp_wait_all() {
    asm volatile("cp.async.wait_group 0;" ::: "memory");
}

// MUFU-free exp for x <= 0: exp(x) = 2^(x*log2e), range-reduced, deg-4 poly.
// Rel err ~4e-5. Runs entirely on fma/alu pipes (no MUFU.EX2).
__device__ __forceinline__ float fast_exp(float x) {
    float t = fmaxf(x * 1.4426950408889634f, -126.0f);
    float r = t + 12582912.0f;                 // 1.5*2^23: round-to-nearest-int
    int   n = __float_as_int(r) - 0x4B400000;  // integer part
    float f = t - (r - 12582912.0f);           // f in [-0.5, 0.5]
    float p = fmaf(f, 0.0096181291f, 0.0555041087f);
    p = fmaf(f, p, 0.2402265069f);
    p = fmaf(f, p, 0.6931471806f);
    p = fmaf(f, p, 1.0f);
    return __int_as_float((n + 127) << 23) * p;
}

// ---------------------------------------------------------------------------
// fp32 -> (hi, lo) bf16 split (streaming, ~11us for activations)
// ---------------------------------------------------------------------------
__global__ __launch_bounds__(256)
void split_bf16(const float* __restrict__ x, __nv_bfloat16* __restrict__ hi,
                __nv_bfloat16* __restrict__ lo, int n4)
{
    int i = blockIdx.x * 256 + threadIdx.x;
    if (i >= n4) return;
    float4 v = ((const float4*)x)[i];
    __nv_bfloat16 h0 = __float2bfloat16_rn(v.x);
    __nv_bfloat16 h1 = __float2bfloat16_rn(v.y);
    __nv_bfloat16 h2 = __float2bfloat16_rn(v.z);
    __nv_bfloat16 h3 = __float2bfloat16_rn(v.w);
    uint2 hv, lv;
    hv.x = pack_bf2(h0, h1);
    hv.y = pack_bf2(h2, h3);
    lv.x = pack_bf2(__float2bfloat16_rn(v.x - __bfloat162float(h0)),
                    __float2bfloat16_rn(v.y - __bfloat162float(h1)));
    lv.y = pack_bf2(__float2bfloat16_rn(v.z - __bfloat162float(h2)),
                    __float2bfloat16_rn(v.w - __bfloat162float(h3)));
    ((uint2*)hi)[i] = hv;
    ((uint2*)lo)[i] = lv;
}

// ---------------------------------------------------------------------------
// GEMM via mma.sync bf16 3-term split, preconverted operands, cp.async
// double-buffered:  Y[M,N] = X[M,K] @ W[N,K]^T + bias
//
// CTA 128x128, 256 thr (8 warps = 4m x 2n), warp tile 32x64, BK=32.
// Buffer layout (48KB each, x2): Ahi@0 Alo@12288 Bhi@24576 Blo@36864;
// each term = 2 k-slabs (16 k each) of 128 rows x 32B, row stride 48B
// (conflict-free ldmatrix — layout identical to the verified R8 kernel).
// ---------------------------------------------------------------------------
#define GBUF 49152
#define GEMM_SMEM (2 * GBUF)

__global__ __launch_bounds__(256)
void gemm_mma(const __nv_bfloat16* __restrict__ Xhi, const __nv_bfloat16* __restrict__ Xlo,
              const __nv_bfloat16* __restrict__ Whi, const __nv_bfloat16* __restrict__ Wlo,
              const float* __restrict__ bias, float* __restrict__ Y)
{
    extern __shared__ char smem[];
    const uint32_t sb = smem_u32(smem);

    const int tid  = threadIdx.x;
    const int lane = tid & 31, wid = tid >> 5;
    const int wm = wid & 3;
    const int wn = wid >> 2;
    const int bm = blockIdx.y * 128, bn = blockIdx.x * 128;

    // Loader: thread t -> row lr (0..127), 16B-half h (0/1) within each slab
    const int lr = tid >> 1;
    const int h  = tid & 1;
    const size_t rowA = (size_t)(bm + lr) * KDIM;
    const size_t rowB = (size_t)(bn + lr) * KDIM;
    const uint32_t dbase = lr * 48 + h * 16;

    // ldmatrix per-lane address patterns (as verified in R8)
    const uint32_t a_off = ((lane & 7) + ((lane >> 3) & 1) * 8) * 48 + ((lane >> 4) & 1) * 16;
    const uint32_t b_off = ((lane & 7) + ((lane >> 4) & 1) * 8) * 48 + ((lane >> 3) & 1) * 16;

    float acc[2][8][4];
#pragma unroll
    for (int mt = 0; mt < 2; mt++)
#pragma unroll
        for (int nt = 0; nt < 8; nt++)
#pragma unroll
            for (int e = 0; e < 4; e++) acc[mt][nt][e] = 0.f;

    // Issue chunk 0 loads
    {
        const int kof = h * 8;   // bf16 elements
#pragma unroll
        for (int s = 0; s < 2; s++) {
            uint32_t d = sb + s * 6144 + dbase;
            int kk = s * 16 + kof;
            cpasync16(d,         Xhi + rowA + kk);
            cpasync16(d + 12288, Xlo + rowA + kk);
            cpasync16(d + 24576, Whi + rowB + kk);
            cpasync16(d + 36864, Wlo + rowB + kk);
        }
        cp_commit();
    }

    for (int c = 0; c < KDIM / 32; c++) {
        cp_wait_all();
        __syncthreads();          // buf (c&1) ready; prev compute done reading other buf

        // Issue next chunk into the other buffer (overlaps with compute below)
        if (c + 1 < KDIM / 32) {
            const uint32_t nb = sb + ((c + 1) & 1) * GBUF;
            const int k0 = (c + 1) * 32 + h * 8;
#pragma unroll
            for (int s = 0; s < 2; s++) {
                uint32_t d = nb + s * 6144 + dbase;
                int kk = k0 + s * 16;
                cpasync16(d,         Xhi + rowA + kk);
                cpasync16(d + 12288, Xlo + rowA + kk);
                cpasync16(d + 24576, Whi + rowB + kk);
                cpasync16(d + 36864, Wlo + rowB + kk);
            }
            cp_commit();
        }

        // Compute on buf (c&1): 2 ksteps x (8 mma-tiles x 3 terms)
        const uint32_t bufb = sb + (c & 1) * GBUF;
#pragma unroll
        for (int s = 0; s < 2; s++) {
            const uint32_t slab = bufb + s * 6144;
            uint32_t aH[2][4], aL[2][4], bH[4][4], bL[4][4];
#pragma unroll
            for (int mt = 0; mt < 2; mt++) {
                uint32_t ad = slab + (uint32_t)(wm * 32 + mt * 16) * 48 + a_off;
                ldsm4(aH[mt], ad);
                ldsm4(aL[mt], ad + 12288);
            }
#pragma unroll
            for (int p = 0; p < 4; p++) {
                uint32_t bd = slab + 24576 + (uint32_t)(wn * 64 + p * 16) * 48 + b_off;
                ldsm4(bH[p], bd);
                ldsm4(bL[p], bd + 12288);
            }
#pragma unroll
            for (int mt = 0; mt < 2; mt++)
#pragma unroll
                for (int p = 0; p < 4; p++)
#pragma unroll
                    for (int hlf = 0; hlf < 2; hlf++) {
                        const int nt = p * 2 + hlf;
                        mma16816(acc[mt][nt], aH[mt], &bH[p][hlf * 2]);
                        mma16816(acc[mt][nt], aH[mt], &bL[p][hlf * 2]);
                        mma16816(acc[mt][nt], aL[mt], &bH[p][hlf * 2]);
                    }
        }
        __syncthreads();          // done reading buf before loader refills it next iter
    }

    // Epilogue: lane holds rows (l>>2, +8), cols (l&3)*2,+1
    const int er = bm + wm * 32 + (lane >> 2);
    const int ec = bn + wn * 64 + (lane & 3) * 2;
#pragma unroll
    for (int mt = 0; mt < 2; mt++)
#pragma unroll
        for (int nt = 0; nt < 8; nt++) {
            int row = er + mt * 16;
            int col = ec + nt * 8;
            float2 bv = *(const float2*)(bias + col);
            *(float2*)(Y + (size_t)row * DMODEL + col) =
                make_float2(acc[mt][nt][0] + bv.x, acc[mt][nt][1] + bv.y);
            *(float2*)(Y + (size_t)(row + 8) * DMODEL + col) =
                make_float2(acc[mt][nt][2] + bv.x, acc[mt][nt][3] + bv.y);
        }
}

// ---------------------------------------------------------------------------
// Flash attention v2 (fp32, online softmax). Identical structure to R8
// (which measured fma=58.9%), with __expf replaced by MUFU-free fast_exp —
// R8 analysis shows MUFU.EX2 (268M calls) co-saturated with FMA.
// ---------------------------------------------------------------------------
#define QS_STRIDE 132
#define KT_STRIDE 68
#define FLASH_SMEM ((64 * QS_STRIDE + 128 * 64 + 64 * 64) * 4)

__global__ __launch_bounds__(256, 2)
void flash2(const float* __restrict__ Q, const float* __restrict__ K,
            const float* __restrict__ V, float* __restrict__ O)
{
    extern __shared__ float fs[];
    float* Qs  = fs;                          // [d][qrow], stride 132
    float* KPs = fs + 64 * QS_STRIDE;         // K^T [d][kcol] stride 68, then P [row][64]
    float* Vs  = KPs + 128 * 64;              // [s][d], stride 64

    const int tid = threadIdx.x;
    const int tx  = tid & 15;                 // 4 cols each (64 total)
    const int ty  = tid >> 4;                 // 8 rows each (128 total)
    const int qbase = blockIdx.x * 128;
    const int h     = blockIdx.y;
    const int b     = blockIdx.z;
    const size_t base = (size_t)b * SEQ * DMODEL + (size_t)h * DHEAD;

    // Load Q tile transposed + pre-scaled by 1/sqrt(64) = 0.125
#pragma unroll
    for (int r = 0; r < 8; r++) {
        int e  = tid + 256 * r;
        int s  = e >> 4;
        int d4 = (e & 15) * 4;
        float4 qv = *(const float4*)(Q + base + (size_t)(qbase + s) * DMODEL + d4);
        Qs[(d4 + 0) * QS_STRIDE + s] = qv.x * 0.125f;
        Qs[(d4 + 1) * QS_STRIDE + s] = qv.y * 0.125f;
        Qs[(d4 + 2) * QS_STRIDE + s] = qv.z * 0.125f;
        Qs[(d4 + 3) * QS_STRIDE + s] = qv.w * 0.125f;
    }

    float m[8], l[8], o[8][4];
#pragma unroll
    for (int i = 0; i < 8; i++) {
        m[i] = -1e30f; l[i] = 0.f;
#pragma unroll
        for (int j = 0; j < 4; j++) o[i][j] = 0.f;
    }

    for (int kt = 0; kt < SEQ / 64; kt++) {
        __syncthreads();

        // Load K tile transposed (stride 68) + V tile natural
#pragma unroll
        for (int r = 0; r < 4; r++) {
            int e  = tid + 256 * r;
            int s  = e >> 4;
            int d4 = (e & 15) * 4;
            size_t goff = base + (size_t)(kt * 64 + s) * DMODEL + d4;
            float4 kv = *(const float4*)(K + goff);
            KPs[(d4 + 0) * KT_STRIDE + s] = kv.x;
            KPs[(d4 + 1) * KT_STRIDE + s] = kv.y;
            KPs[(d4 + 2) * KT_STRIDE + s] = kv.z;
            KPs[(d4 + 3) * KT_STRIDE + s] = kv.w;
            *(float4*)&Vs[s * 64 + d4] = *(const float4*)(V + goff);
        }
        __syncthreads();

        // S = (Q/8) @ K^T
        float sc[8][4];
#pragma unroll
        for (int i = 0; i < 8; i++)
#pragma unroll
            for (int j = 0; j < 4; j++) sc[i][j] = 0.f;

#pragma unroll 8
        for (int d = 0; d < 64; d++) {
            float4 qa0 = *(const float4*)&Qs[d * QS_STRIDE + ty * 8];
            float4 qa1 = *(const float4*)&Qs[d * QS_STRIDE + ty * 8 + 4];
            float4 kb  = *(const float4*)&KPs[d * KT_STRIDE + tx * 4];
            float a[8]  = {qa0.x, qa0.y, qa0.z, qa0.w, qa1.x, qa1.y, qa1.z, qa1.w};
            float bb[4] = {kb.x, kb.y, kb.z, kb.w};
#pragma unroll
            for (int i = 0; i < 8; i++)
#pragma unroll
                for (int j = 0; j < 4; j++)
                    sc[i][j] = fmaf(a[i], bb[j], sc[i][j]);
        }

        // Online softmax (MUFU-free exp); 16-lane xor reductions per row
#pragma unroll
        for (int i = 0; i < 8; i++) {
            float rm = fmaxf(fmaxf(sc[i][0], sc[i][1]), fmaxf(sc[i][2], sc[i][3]));
#pragma unroll
            for (int off = 1; off < 16; off <<= 1)
                rm = fmaxf(rm, __shfl_xor_sync(0xffffffffu, rm, off));
            float mn   = fmaxf(m[i], rm);
            float corr = fast_exp(m[i] - mn);
            float rs   = 0.f;
#pragma unroll
            for (int j = 0; j < 4; j++) {
                float p = fast_exp(sc[i][j] - mn);
                sc[i][j] = p;
                rs += p;
            }
#pragma unroll
            for (int off = 1; off < 16; off <<= 1)
                rs += __shfl_xor_sync(0xffffffffu, rs, off);
            l[i] = l[i] * corr + rs;
            m[i] = mn;
#pragma unroll
            for (int j = 0; j < 4; j++) o[i][j] *= corr;
        }

        __syncthreads();

        // P [qrow][kcol], stride 64
#pragma unroll
        for (int i = 0; i < 8; i++)
            *(float4*)&KPs[(ty * 8 + i) * 64 + tx * 4] =
                make_float4(sc[i][0], sc[i][1], sc[i][2], sc[i][3]);
        __syncthreads();

        // O += P @ V
#pragma unroll 8
        for (int kk = 0; kk < 64; kk++) {
            float4 vb = *(const float4*)&Vs[kk * 64 + tx * 4];
#pragma unroll
            for (int i = 0; i < 8; i++) {
                float pa = KPs[(ty * 8 + i) * 64 + kk];
                o[i][0] = fmaf(pa, vb.x, o[i][0]);
                o[i][1] = fmaf(pa, vb.y, o[i][1]);
                o[i][2] = fmaf(pa, vb.z, o[i][2]);
                o[i][3] = fmaf(pa, vb.w, o[i][3]);
            }
        }
    }

    // Normalize and write context in merged [B,S,D] layout
#pragma unroll
    for (int i = 0; i < 8; i++) {
        float inv = 1.0f / l[i];
        float* op = O + base + (size_t)(qbase + ty * 8 + i) * DMODEL + tx * 4;
        *(float4*)op = make_float4(o[i][0] * inv, o[i][1] * inv,
                                   o[i][2] * inv, o[i][3] * inv);
    }
}

// ---------------------------------------------------------------------------
// Launch. Input order: v, k, q, wq_w, wq_b, wk_w, wk_b, wv_w, wv_b,
//                      dense_w, dense_b
// ---------------------------------------------------------------------------
extern "C" void kernel_launch(void* const* d_in, const int* in_sizes, int n_in,
                              void* d_out, int out_size)
{
    const float* v    = (const float*)d_in[0];
    const float* k    = (const float*)d_in[1];
    const float* q    = (const float*)d_in[2];
    const float* wq_w = (const float*)d_in[3];
    const float* wq_b = (const float*)d_in[4];
    const float* wk_w = (const float*)d_in[5];
    const float* wk_b = (const float*)d_in[6];
    const float* wv_w = (const float*)d_in[7];
    const float* wv_b = (const float*)d_in[8];
    const float* dw   = (const float*)d_in[9];
    const float* db   = (const float*)d_in[10];

    float *gq, *gk, *gv, *gctx;
    __nv_bfloat16 *aHi, *aLo, *bHi, *bLo;
    cudaGetSymbolAddress((void**)&gq,   g_q);
    cudaGetSymbolAddress((void**)&gk,   g_k);
    cudaGetSymbolAddress((void**)&gv,   g_v);
    cudaGetSymbolAddress((void**)&gctx, g_ctx);
    cudaGetSymbolAddress((void**)&aHi,  g_aHi);
    cudaGetSymbolAddress((void**)&aLo,  g_aLo);
    cudaGetSymbolAddress((void**)&bHi,  g_bHi);
    cudaGetSymbolAddress((void**)&bLo,  g_bLo);

    cudaFuncSetAttribute(gemm_mma, cudaFuncAttributeMaxDynamicSharedMemorySize, GEMM_SMEM);
    cudaFuncSetAttribute(flash2,   cudaFuncAttributeMaxDynamicSharedMemorySize, FLASH_SMEM);

    const int nx4 = MTOT * DMODEL / 4;
    const int nw4 = DMODEL * DMODEL / 4;
    dim3 gsx(nx4 / 256), gsw(nw4 / 256);
    dim3 gg(DMODEL / 128, MTOT / 128);
    dim3 bt(256);

    // Q projection
    split_bf16<<<gsx, bt>>>(q, aHi, aLo, nx4);
    split_bf16<<<gsw, bt>>>(wq_w, bHi, bLo, nw4);
    gemm_mma<<<gg, bt, GEMM_SMEM>>>(aHi, aLo, bHi, bLo, wq_b, gq);
    // K projection
    split_bf16<<<gsx, bt>>>(k, aHi, aLo, nx4);
    split_bf16<<<gsw, bt>>>(wk_w, bHi, bLo, nw4);
    gemm_mma<<<gg, bt, GEMM_SMEM>>>(aHi, aLo, bHi, bLo, wk_b, gk);
    // V projection
    split_bf16<<<gsx, bt>>>(v, aHi, aLo, nx4);
    split_bf16<<<gsw, bt>>>(wv_w, bHi, bLo, nw4);
    gemm_mma<<<gg, bt, GEMM_SMEM>>>(aHi, aLo, bHi, bLo, wv_b, gv);

    // Attention
    dim3 ga(SEQ / 128, NHEAD, BATCH);
    flash2<<<ga, bt, FLASH_SMEM>>>(gq, gk, gv, gctx);

    // Dense
    split_bf16<<<gsx, bt>>>(gctx, aHi, aLo, nx4);
    split_bf16<<<gsw, bt>>>(dw, bHi, bLo, nw4);
    gemm_mma<<<gg, bt, GEMM_SMEM>>>(aHi, aLo, bHi, bLo, db, (float*)d_out);
}

// round 12
// speedup vs baseline: 1.8251x; 1.8251x over previous
#include <cuda_runtime.h>
#include <cuda_bf16.h>
#include <cstdint>

// Problem constants
#define BATCH  4
#define SEQ    2048
#define DMODEL 1024
#define NHEAD  16
#define DHEAD  64
#define MTOT   (BATCH * SEQ)   // 8192 rows
#define KDIM   DMODEL

// ---------------------------------------------------------------------------
// Scratch (__device__ globals — the sanctioned no-alloc path). All bf16 hi/lo.
// ---------------------------------------------------------------------------
__device__ __nv_bfloat16 g_aHi[(size_t)MTOT * DMODEL];
__device__ __nv_bfloat16 g_aLo[(size_t)MTOT * DMODEL];
__device__ __nv_bfloat16 g_bHi[(size_t)DMODEL * DMODEL];
__device__ __nv_bfloat16 g_bLo[(size_t)DMODEL * DMODEL];
__device__ __nv_bfloat16 g_qHi[(size_t)MTOT * DMODEL];
__device__ __nv_bfloat16 g_qLo[(size_t)MTOT * DMODEL];
__device__ __nv_bfloat16 g_kHi[(size_t)MTOT * DMODEL];
__device__ __nv_bfloat16 g_kLo[(size_t)MTOT * DMODEL];
__device__ __nv_bfloat16 g_vHi[(size_t)MTOT * DMODEL];
__device__ __nv_bfloat16 g_vLo[(size_t)MTOT * DMODEL];
__device__ __nv_bfloat16 g_cHi[(size_t)MTOT * DMODEL];
__device__ __nv_bfloat16 g_cLo[(size_t)MTOT * DMODEL];

// ---------------------------------------------------------------------------
// Helpers (baseline compute_103 PTX only — no tcgen05/TMEM in this harness)
// ---------------------------------------------------------------------------
__device__ __forceinline__ uint32_t smem_u32(const void* p) {
    uint32_t a;
    asm("{ .reg .u64 t; cvta.to.shared.u64 t, %1; cvt.u32.u64 %0, t; }"
        : "=r"(a) : "l"(p));
    return a;
}
__device__ __forceinline__ void ldsm4(uint32_t* r, uint32_t addr) {
    asm volatile("ldmatrix.sync.aligned.m8n8.x4.shared.b16 {%0,%1,%2,%3}, [%4];"
                 : "=r"(r[0]), "=r"(r[1]), "=r"(r[2]), "=r"(r[3]) : "r"(addr));
}
__device__ __forceinline__ void ldsm4t(uint32_t* r, uint32_t addr) {
    asm volatile("ldmatrix.sync.aligned.m8n8.x4.trans.shared.b16 {%0,%1,%2,%3}, [%4];"
                 : "=r"(r[0]), "=r"(r[1]), "=r"(r[2]), "=r"(r[3]) : "r"(addr));
}
__device__ __forceinline__ void mma16816(float* d, const uint32_t* a, const uint32_t* b) {
    asm volatile(
        "mma.sync.aligned.m16n8k16.row.col.f32.bf16.bf16.f32 "
        "{%0,%1,%2,%3}, {%4,%5,%6,%7}, {%8,%9}, {%0,%1,%2,%3};"
        : "+f"(d[0]), "+f"(d[1]), "+f"(d[2]), "+f"(d[3])
        : "r"(a[0]), "r"(a[1]), "r"(a[2]), "r"(a[3]), "r"(b[0]), "r"(b[1]));
}
__device__ __forceinline__ uint32_t pack_bf2(__nv_bfloat16 a, __nv_bfloat16 b) {
    __nv_bfloat162 t = __halves2bfloat162(a, b);
    return *(uint32_t*)&t;
}
__device__ __forceinline__ void cpasync16(uint32_t dst, const void* src) {
    asm volatile("cp.async.ca.shared.global [%0], [%1], 16;"
                 :: "r"(dst), "l"(src) : "memory");
}
__device__ __forceinline__ void cp_commit() {
    asm volatile("cp.async.commit_group;" ::: "memory");
}
__device__ __forceinline__ void cp_wait0() {
    asm volatile("cp.async.wait_group 0;" ::: "memory");
}
__device__ __forceinline__ void cp_wait1() {
    asm volatile("cp.async.wait_group 1;" ::: "memory");
}

// exp(x/8) for x <= 0, MUFU-free (verified R11): 2^(x*log2e/8), deg-4 poly.
__device__ __forceinline__ float fexp8(float x) {
    float t = fmaxf(x * 0.18033688011112043f, -126.0f);
    float r = t + 12582912.0f;
    int   n = __float_as_int(r) - 0x4B400000;
    float f = t - (r - 12582912.0f);
    float p = fmaf(f, 0.0096181291f, 0.0555041087f);
    p = fmaf(f, p, 0.2402265069f);
    p = fmaf(f, p, 0.6931471806f);
    p = fmaf(f, p, 1.0f);
    return __int_as_float((n + 127) << 23) * p;
}

// ---------------------------------------------------------------------------
// fp32 -> (hi, lo) bf16 split (streaming)
// ---------------------------------------------------------------------------
__global__ __launch_bounds__(256)
void split_bf16(const float* __restrict__ x, __nv_bfloat16* __restrict__ hi,
                __nv_bfloat16* __restrict__ lo, int n4)
{
    int i = blockIdx.x * 256 + threadIdx.x;
    if (i >= n4) return;
    float4 v = ((const float4*)x)[i];
    __nv_bfloat16 h0 = __float2bfloat16_rn(v.x);
    __nv_bfloat16 h1 = __float2bfloat16_rn(v.y);
    __nv_bfloat16 h2 = __float2bfloat16_rn(v.z);
    __nv_bfloat16 h3 = __float2bfloat16_rn(v.w);
    uint2 hv, lv;
    hv.x = pack_bf2(h0, h1);
    hv.y = pack_bf2(h2, h3);
    lv.x = pack_bf2(__float2bfloat16_rn(v.x - __bfloat162float(h0)),
                    __float2bfloat16_rn(v.y - __bfloat162float(h1)));
    lv.y = pack_bf2(__float2bfloat16_rn(v.z - __bfloat162float(h2)),
                    __float2bfloat16_rn(v.w - __bfloat162float(h3)));
    ((uint2*)hi)[i] = hv;
    ((uint2*)lo)[i] = lv;
}

// ---------------------------------------------------------------------------
// GEMM via mma.sync bf16 3-term split (verified R11 body).
// OUTMODE 0: fp32 out (Yf).  OUTMODE 1: bf16 hi/lo out (Yhi/Ylo).
// ---------------------------------------------------------------------------
#define GBUF 49152
#define GEMM_SMEM (2 * GBUF)

template<int OUTMODE>
__global__ __launch_bounds__(256)
void gemm_mma(const __nv_bfloat16* __restrict__ Xhi, const __nv_bfloat16* __restrict__ Xlo,
              const __nv_bfloat16* __restrict__ Whi, const __nv_bfloat16* __restrict__ Wlo,
              const float* __restrict__ bias, float* __restrict__ Yf,
              __nv_bfloat16* __restrict__ Yhi, __nv_bfloat16* __restrict__ Ylo)
{
    extern __shared__ char smem[];
    const uint32_t sb = smem_u32(smem);

    const int tid  = threadIdx.x;
    const int lane = tid & 31, wid = tid >> 5;
    const int wm = wid & 3;
    const int wn = wid >> 2;
    const int bm = blockIdx.y * 128, bn = blockIdx.x * 128;

    const int lr = tid >> 1;
    const int h  = tid & 1;
    const size_t rowA = (size_t)(bm + lr) * KDIM;
    const size_t rowB = (size_t)(bn + lr) * KDIM;
    const uint32_t dbase = lr * 48 + h * 16;

    const uint32_t a_off = ((lane & 7) + ((lane >> 3) & 1) * 8) * 48 + ((lane >> 4) & 1) * 16;
    const uint32_t b_off = ((lane & 7) + ((lane >> 4) & 1) * 8) * 48 + ((lane >> 3) & 1) * 16;

    float acc[2][8][4];
#pragma unroll
    for (int mt = 0; mt < 2; mt++)
#pragma unroll
        for (int nt = 0; nt < 8; nt++)
#pragma unroll
            for (int e = 0; e < 4; e++) acc[mt][nt][e] = 0.f;

    {
        const int kof = h * 8;
#pragma unroll
        for (int s = 0; s < 2; s++) {
            uint32_t d = sb + s * 6144 + dbase;
            int kk = s * 16 + kof;
            cpasync16(d,         Xhi + rowA + kk);
            cpasync16(d + 12288, Xlo + rowA + kk);
            cpasync16(d + 24576, Whi + rowB + kk);
            cpasync16(d + 36864, Wlo + rowB + kk);
        }
        cp_commit();
    }

    for (int c = 0; c < KDIM / 32; c++) {
        cp_wait0();
        __syncthreads();

        if (c + 1 < KDIM / 32) {
            const uint32_t nb = sb + ((c + 1) & 1) * GBUF;
            const int k0 = (c + 1) * 32 + h * 8;
#pragma unroll
            for (int s = 0; s < 2; s++) {
                uint32_t d = nb + s * 6144 + dbase;
                int kk = k0 + s * 16;
                cpasync16(d,         Xhi + rowA + kk);
                cpasync16(d + 12288, Xlo + rowA + kk);
                cpasync16(d + 24576, Whi + rowB + kk);
                cpasync16(d + 36864, Wlo + rowB + kk);
            }
            cp_commit();
        }

        const uint32_t bufb = sb + (c & 1) * GBUF;
#pragma unroll
        for (int s = 0; s < 2; s++) {
            const uint32_t slab = bufb + s * 6144;
            uint32_t aH[2][4], aL[2][4], bH[4][4], bL[4][4];
#pragma unroll
            for (int mt = 0; mt < 2; mt++) {
                uint32_t ad = slab + (uint32_t)(wm * 32 + mt * 16) * 48 + a_off;
                ldsm4(aH[mt], ad);
                ldsm4(aL[mt], ad + 12288);
            }
#pragma unroll
            for (int p = 0; p < 4; p++) {
                uint32_t bd = slab + 24576 + (uint32_t)(wn * 64 + p * 16) * 48 + b_off;
                ldsm4(bH[p], bd);
                ldsm4(bL[p], bd + 12288);
            }
#pragma unroll
            for (int mt = 0; mt < 2; mt++)
#pragma unroll
                for (int p = 0; p < 4; p++)
#pragma unroll
                    for (int hlf = 0; hlf < 2; hlf++) {
                        const int nt = p * 2 + hlf;
                        mma16816(acc[mt][nt], aH[mt], &bH[p][hlf * 2]);
                        mma16816(acc[mt][nt], aH[mt], &bL[p][hlf * 2]);
                        mma16816(acc[mt][nt], aL[mt], &bH[p][hlf * 2]);
                    }
        }
        __syncthreads();
    }

    const int er = bm + wm * 32 + (lane >> 2);
    const int ec = bn + wn * 64 + (lane & 3) * 2;
#pragma unroll
    for (int mt = 0; mt < 2; mt++)
#pragma unroll
        for (int nt = 0; nt < 8; nt++) {
            int row = er + mt * 16;
            int col = ec + nt * 8;
            float2 bv = *(const float2*)(bias + col);
            float y00 = acc[mt][nt][0] + bv.x, y01 = acc[mt][nt][1] + bv.y;
            float y10 = acc[mt][nt][2] + bv.x, y11 = acc[mt][nt][3] + bv.y;
            if (OUTMODE == 0) {
                *(float2*)(Yf + (size_t)row * DMODEL + col) = make_float2(y00, y01);
                *(float2*)(Yf + (size_t)(row + 8) * DMODEL + col) = make_float2(y10, y11);
            } else {
                __nv_bfloat16 h00 = __float2bfloat16_rn(y00), h01 = __float2bfloat16_rn(y01);
                __nv_bfloat16 h10 = __float2bfloat16_rn(y10), h11 = __float2bfloat16_rn(y11);
                *(uint32_t*)(Yhi + (size_t)row * DMODEL + col)       = pack_bf2(h00, h01);
                *(uint32_t*)(Yhi + (size_t)(row + 8) * DMODEL + col) = pack_bf2(h10, h11);
                *(uint32_t*)(Ylo + (size_t)row * DMODEL + col) = pack_bf2(
                    __float2bfloat16_rn(y00 - __bfloat162float(h00)),
                    __float2bfloat16_rn(y01 - __bfloat162float(h01)));
                *(uint32_t*)(Ylo + (size_t)(row + 8) * DMODEL + col) = pack_bf2(
                    __float2bfloat16_rn(y10 - __bfloat162float(h10)),
                    __float2bfloat16_rn(y11 - __bfloat162float(h11)));
            }
        }
}

// ---------------------------------------------------------------------------
// Flash attention v3: both matmuls on mma.sync bf16 (3-term hi/lo split),
// FA2-style softmax in fragment layout, P kept in registers.
//
// CTA: 128 q-rows, 8 warps x 16 rows, kt-tile = 64 keys. N(S tile)=64.
// Smem: rows stride 144B. Q hi/lo staged once in buf0 (36864B) then the two
// 36864B buffers double-buffer K/V hi/lo tiles (K natural = B layout for QK;
// V natural consumed via ldmatrix.trans for PV). All loads cp.async.
// ---------------------------------------------------------------------------
#define FL_ROWB 144
#define FL_KHI 0
#define FL_KLO (64 * FL_ROWB)        // 9216
#define FL_VHI (2 * 64 * FL_ROWB)    // 18432
#define FL_VLO (3 * 64 * FL_ROWB)    // 27648
#define FL_BUF (4 * 64 * FL_ROWB)    // 36864
#define FLASH_SMEM (2 * FL_BUF)      // 73728

__global__ __launch_bounds__(256, 1)
void flash3(const __nv_bfloat16* __restrict__ Qhi, const __nv_bfloat16* __restrict__ Qlo,
            const __nv_bfloat16* __restrict__ Khi, const __nv_bfloat16* __restrict__ Klo,
            const __nv_bfloat16* __restrict__ Vhi, const __nv_bfloat16* __restrict__ Vlo,
            __nv_bfloat16* __restrict__ OHi, __nv_bfloat16* __restrict__ OLo)
{
    extern __shared__ char smem[];
    const uint32_t sb = smem_u32(smem);
    const int tid = threadIdx.x, lane = tid & 31, wid = tid >> 5;
    const int qbase = blockIdx.x * 128;
    const int hh = blockIdx.y, b = blockIdx.z;
    const size_t base = (size_t)b * SEQ * DMODEL + (size_t)hh * DHEAD;

    // ---- Stage Q hi/lo into buf0, extract A-fragments, then free the region
#pragma unroll
    for (int j = 0; j < 4; j++) {
        int e = tid + 256 * j;           // 0..1023
        int row = e >> 3, ch = e & 7;    // 128 rows x 8 chunks(16B)
        size_t g = base + (size_t)(qbase + row) * DMODEL + ch * 8;
        cpasync16(sb + row * FL_ROWB + ch * 16, Qhi + g);
        cpasync16(sb + 18432 + row * FL_ROWB + ch * 16, Qlo + g);
    }
    cp_commit();
    cp_wait0();
    __syncthreads();

    uint32_t qh[4][4], ql[4][4];
    {
        uint32_t ab = sb + (uint32_t)(wid * 16 + (lane & 15)) * FL_ROWB + ((lane >> 4) & 1) * 16;
#pragma unroll
        for (int kc = 0; kc < 4; kc++) {
            ldsm4(qh[kc], ab + kc * 32);
            ldsm4(ql[kc], ab + kc * 32 + 18432);
        }
    }
    __syncthreads();   // Q region becomes K/V buf0

    // K/V tile loader (all cp.async, 16B): 64 rows x 8 chunks per term
    auto load_tile = [&](int kt, int bufIdx) {
        const uint32_t bb = sb + bufIdx * FL_BUF;
        const size_t rb = base + (size_t)(kt * 64) * DMODEL;
#pragma unroll
        for (int j = 0; j < 2; j++) {
            int e = tid + 256 * j;        // 0..511
            int row = e >> 3, ch = e & 7;
            size_t g = rb + (size_t)row * DMODEL + ch * 8;
            uint32_t d = bb + row * FL_ROWB + ch * 16;
            cpasync16(d + FL_KHI, Khi + g);
            cpasync16(d + FL_KLO, Klo + g);
            cpasync16(d + FL_VHI, Vhi + g);
            cpasync16(d + FL_VLO, Vlo + g);
        }
        cp_commit();
    };
    load_tile(0, 0);

    float m0 = -1e30f, m1 = -1e30f, l0 = 0.f, l1 = 0.f;
    float o[8][4];
#pragma unroll
    for (int nt = 0; nt < 8; nt++)
#pragma unroll
        for (int e = 0; e < 4; e++) o[nt][e] = 0.f;

    // ldmatrix per-lane base offsets
    const uint32_t kb_off = (uint32_t)((lane & 7) + ((lane >> 4) & 1) * 8) * FL_ROWB
                          + ((lane >> 3) & 1) * 16;                   // K (B, non-trans)
    const uint32_t vb_off = (uint32_t)(lane & 15) * FL_ROWB
                          + ((lane >> 4) & 1) * 16;                   // V (B, trans)

    for (int kt = 0; kt < SEQ / 64; kt++) {
        const int cur = kt & 1;
        if (kt + 1 < SEQ / 64) { load_tile(kt + 1, cur ^ 1); cp_wait1(); }
        else                   { cp_wait0(); }
        __syncthreads();
        const uint32_t bb = sb + cur * FL_BUF;

        // ---- S = Q @ K^T (3-term), S in D-fragments sc[nt][0..3]
        float sc[8][4];
#pragma unroll
        for (int nt = 0; nt < 8; nt++)
#pragma unroll
            for (int e = 0; e < 4; e++) sc[nt][e] = 0.f;

#pragma unroll
        for (int kc = 0; kc < 4; kc++) {
#pragma unroll
            for (int p = 0; p < 4; p++) {
                uint32_t bKh[4], bKl[4];
                uint32_t ad = bb + kb_off + (uint32_t)(p * 16) * FL_ROWB + kc * 32;
                ldsm4(bKh, ad + FL_KHI);
                ldsm4(bKl, ad + FL_KLO);
#pragma unroll
                for (int hf = 0; hf < 2; hf++)
                    mma16816(sc[p * 2 + hf], qh[kc], &bKh[hf * 2]);
#pragma unroll
                for (int hf = 0; hf < 2; hf++)
                    mma16816(sc[p * 2 + hf], qh[kc], &bKl[hf * 2]);
#pragma unroll
                for (int hf = 0; hf < 2; hf++)
                    mma16816(sc[p * 2 + hf], ql[kc], &bKh[hf * 2]);
            }
        }

        // ---- Online softmax in fragment layout (rows r0 = l>>2, r1 = r0+8)
        float rm0 = -1e30f, rm1 = -1e30f;
#pragma unroll
        for (int nt = 0; nt < 8; nt++) {
            rm0 = fmaxf(rm0, fmaxf(sc[nt][0], sc[nt][1]));
            rm1 = fmaxf(rm1, fmaxf(sc[nt][2], sc[nt][3]));
        }
        rm0 = fmaxf(rm0, __shfl_xor_sync(0xffffffffu, rm0, 1));
        rm0 = fmaxf(rm0, __shfl_xor_sync(0xffffffffu, rm0, 2));
        rm1 = fmaxf(rm1, __shfl_xor_sync(0xffffffffu, rm1, 1));
        rm1 = fmaxf(rm1, __shfl_xor_sync(0xffffffffu, rm1, 2));
        float mn0 = fmaxf(m0, rm0), mn1 = fmaxf(m1, rm1);
        float c0 = fexp8(m0 - mn0), c1 = fexp8(m1 - mn1);
        float rs0 = 0.f, rs1 = 0.f;
#pragma unroll
        for (int nt = 0; nt < 8; nt++) {
            sc[nt][0] = fexp8(sc[nt][0] - mn0);
            sc[nt][1] = fexp8(sc[nt][1] - mn0);
            sc[nt][2] = fexp8(sc[nt][2] - mn1);
            sc[nt][3] = fexp8(sc[nt][3] - mn1);
            rs0 += sc[nt][0] + sc[nt][1];
            rs1 += sc[nt][2] + sc[nt][3];
        }
        rs0 += __shfl_xor_sync(0xffffffffu, rs0, 1);
        rs0 += __shfl_xor_sync(0xffffffffu, rs0, 2);
        rs1 += __shfl_xor_sync(0xffffffffu, rs1, 1);
        rs1 += __shfl_xor_sync(0xffffffffu, rs1, 2);
        l0 = l0 * c0 + rs0;  l1 = l1 * c1 + rs1;
        m0 = mn0;  m1 = mn1;
#pragma unroll
        for (int nt = 0; nt < 8; nt++) {
            o[nt][0] *= c0; o[nt][1] *= c0;
            o[nt][2] *= c1; o[nt][3] *= c1;
        }

        // ---- Pack P: S D-fragment == P A-fragment (hi/lo)
        uint32_t ph[4][4], pl[4][4];
#pragma unroll
        for (int kc = 0; kc < 4; kc++) {
#pragma unroll
            for (int half = 0; half < 2; half++) {      // k-lo (nt=2kc) / k-hi (nt=2kc+1)
                const int nt = kc * 2 + half;
#pragma unroll
                for (int rr = 0; rr < 2; rr++) {        // r0 regs / r1 regs
                    float p0 = sc[nt][rr * 2 + 0], p1 = sc[nt][rr * 2 + 1];
                    __nv_bfloat16 b0 = __float2bfloat16_rn(p0);
                    __nv_bfloat16 b1 = __float2bfloat16_rn(p1);
                    ph[kc][half * 2 + rr] = pack_bf2(b0, b1);
                    pl[kc][half * 2 + rr] = pack_bf2(
                        __float2bfloat16_rn(p0 - __bfloat162float(b0)),
                        __float2bfloat16_rn(p1 - __bfloat162float(b1)));
                }
            }
        }

        // ---- O += P @ V (3-term), V via ldmatrix.trans on natural [s][d]
#pragma unroll
        for (int kc = 0; kc < 4; kc++) {
#pragma unroll
            for (int dp = 0; dp < 4; dp++) {
                uint32_t vH[4], vL[4];
                uint32_t ad = bb + vb_off + (uint32_t)(kc * 16) * FL_ROWB + dp * 32;
                ldsm4t(vH, ad + FL_VHI);
                ldsm4t(vL, ad + FL_VLO);
#pragma unroll
                for (int hf = 0; hf < 2; hf++)
                    mma16816(o[dp * 2 + hf], ph[kc], &vH[hf * 2]);
#pragma unroll
                for (int hf = 0; hf < 2; hf++)
                    mma16816(o[dp * 2 + hf], ph[kc], &vL[hf * 2]);
#pragma unroll
                for (int hf = 0; hf < 2; hf++)
                    mma16816(o[dp * 2 + hf], pl[kc], &vH[hf * 2]);
            }
        }
        __syncthreads();   // all ldsm done before next tile overwrites buf
    }

    // ---- Normalize, split hi/lo, store ctx (merged [B,S,D] layout)
    const float i0 = 1.0f / l0, i1 = 1.0f / l1;
    const int r0 = qbase + wid * 16 + (lane >> 2);
#pragma unroll
    for (int nt = 0; nt < 8; nt++) {
        const int col = nt * 8 + (lane & 3) * 2;
        float y00 = o[nt][0] * i0, y01 = o[nt][1] * i0;
        float y10 = o[nt][2] * i1, y11 = o[nt][3] * i1;
        __nv_bfloat16 h00 = __float2bfloat16_rn(y00), h01 = __float2bfloat16_rn(y01);
        __nv_bfloat16 h10 = __float2bfloat16_rn(y10), h11 = __float2bfloat16_rn(y11);
        size_t a0 = base + (size_t)r0 * DMODEL + col;
        size_t a1 = base + (size_t)(r0 + 8) * DMODEL + col;
        *(uint32_t*)(OHi + a0) = pack_bf2(h00, h01);
        *(uint32_t*)(OHi + a1) = pack_bf2(h10, h11);
        *(uint32_t*)(OLo + a0) = pack_bf2(
            __float2bfloat16_rn(y00 - __bfloat162float(h00)),
            __float2bfloat16_rn(y01 - __bfloat162float(h01)));
        *(uint32_t*)(OLo + a1) = pack_bf2(
            __float2bfloat16_rn(y10 - __bfloat162float(h10)),
            __float2bfloat16_rn(y11 - __bfloat162float(h11)));
    }
}

// ---------------------------------------------------------------------------
// Launch. Input order: v, k, q, wq_w, wq_b, wk_w, wk_b, wv_w, wv_b,
//                      dense_w, dense_b
// ---------------------------------------------------------------------------
extern "C" void kernel_launch(void* const* d_in, const int* in_sizes, int n_in,
                              void* d_out, int out_size)
{
    const float* v    = (const float*)d_in[0];
    const float* k    = (const float*)d_in[1];
    const float* q    = (const float*)d_in[2];
    const float* wq_w = (const float*)d_in[3];
    const float* wq_b = (const float*)d_in[4];
    const float* wk_w = (const float*)d_in[5];
    const float* wk_b = (const float*)d_in[6];
    const float* wv_w = (const float*)d_in[7];
    const float* wv_b = (const float*)d_in[8];
    const float* dw   = (const float*)d_in[9];
    const float* db   = (const float*)d_in[10];

    __nv_bfloat16 *aHi, *aLo, *bHi, *bLo;
    __nv_bfloat16 *qHi, *qLo, *kHi, *kLo, *vHi, *vLo, *cHi, *cLo;
    cudaGetSymbolAddress((void**)&aHi, g_aHi);
    cudaGetSymbolAddress((void**)&aLo, g_aLo);
    cudaGetSymbolAddress((void**)&bHi, g_bHi);
    cudaGetSymbolAddress((void**)&bLo, g_bLo);
    cudaGetSymbolAddress((void**)&qHi, g_qHi);
    cudaGetSymbolAddress((void**)&qLo, g_qLo);
    cudaGetSymbolAddress((void**)&kHi, g_kHi);
    cudaGetSymbolAddress((void**)&kLo, g_kLo);
    cudaGetSymbolAddress((void**)&vHi, g_vHi);
    cudaGetSymbolAddress((void**)&vLo, g_vLo);
    cudaGetSymbolAddress((void**)&cHi, g_cHi);
    cudaGetSymbolAddress((void**)&cLo, g_cLo);

    cudaFuncSetAttribute(gemm_mma<0>, cudaFuncAttributeMaxDynamicSharedMemorySize, GEMM_SMEM);
    cudaFuncSetAttribute(gemm_mma<1>, cudaFuncAttributeMaxDynamicSharedMemorySize, GEMM_SMEM);
    cudaFuncSetAttribute(flash3,      cudaFuncAttributeMaxDynamicSharedMemorySize, FLASH_SMEM);

    const int nx4 = MTOT * DMODEL / 4;
    const int nw4 = DMODEL * DMODEL / 4;
    dim3 gsx(nx4 / 256), gsw(nw4 / 256);
    dim3 gg(DMODEL / 128, MTOT / 128);
    dim3 bt(256);

    // Q projection -> bf16 hi/lo
    split_bf16<<<gsx, bt>>>(q, aHi, aLo, nx4);
    split_bf16<<<gsw, bt>>>(wq_w, bHi, bLo, nw4);
    gemm_mma<1><<<gg, bt, GEMM_SMEM>>>(aHi, aLo, bHi, bLo, wq_b, nullptr, qHi, qLo);
    // K projection
    split_bf16<<<gsx, bt>>>(k, aHi, aLo, nx4);
    split_bf16<<<gsw, bt>>>(wk_w, bHi, bLo, nw4);
    gemm_mma<1><<<gg, bt, GEMM_SMEM>>>(aHi, aLo, bHi, bLo, wk_b, nullptr, kHi, kLo);
    // V projection
    split_bf16<<<gsx, bt>>>(v, aHi, aLo, nx4);
    split_bf16<<<gsw, bt>>>(wv_w, bHi, bLo, nw4);
    gemm_mma<1><<<gg, bt, GEMM_SMEM>>>(aHi, aLo, bHi, bLo, wv_b, nullptr, vHi, vLo);

    // Attention (tensor-core flash, ctx out as hi/lo)
    dim3 ga(SEQ / 128, NHEAD, BATCH);
    flash3<<<ga, bt, FLASH_SMEM>>>(qHi, qLo, kHi, kLo, vHi, vLo, cHi, cLo);

    // Dense -> fp32 d_out
    split_bf16<<<gsw, bt>>>(dw, bHi, bLo, nw4);
    gemm_mma<0><<<gg, bt, GEMM_SMEM>>>(cHi, cLo, bHi, bLo, db, (float*)d_out, nullptr, nullptr);
}